// round 15
// baseline (speedup 1.0000x reference)
#include <cuda_runtime.h>
#include <cuda_bf16.h>
#include <cstdint>

#define MAXN 50000
#define MAXE 800000
#define FD   128
#define HD   128
#define OD   256

// ---------------- device scratch ----------------
__device__ float g_sum[(size_t)MAXN * FD];
__device__ int   g_cnt[MAXN];
__device__ float g_P[(size_t)MAXN * 512];
__device__ float g_Wcat[512 * 128];

// ---------------- tf32 helpers (baseline PTX, works on compute_103) -------
__device__ __forceinline__ void split_tf32(float x, uint32_t& hi, uint32_t& lo) {
    asm("cvt.rna.tf32.f32 %0, %1;" : "=r"(hi) : "f"(x));
    float r = x - __uint_as_float(hi);
    asm("cvt.rna.tf32.f32 %0, %1;" : "=r"(lo) : "f"(r));
}
__device__ __forceinline__ void mma_m16n8k8(float* c, const uint32_t* a,
                                            const uint32_t* b) {
    asm volatile(
        "mma.sync.aligned.m16n8k8.row.col.f32.tf32.tf32.f32 "
        "{%0,%1,%2,%3}, {%4,%5,%6,%7}, {%8,%9}, {%0,%1,%2,%3};"
        : "+f"(c[0]), "+f"(c[1]), "+f"(c[2]), "+f"(c[3])
        : "r"(a[0]), "r"(a[1]), "r"(a[2]), "r"(a[3]), "r"(b[0]), "r"(b[1]));
}

// ---------------- smem layout (float words), stride 136 -------------------
#define SMS   136
#define S1_AH 0
#define S1_AL 8704            // 64*136
#define S1_BH 17408
#define S1_BL 26112
#define HS_H  0               // reuses stage-1 A/B region after stage 1
#define HS_L  17408           // 128*136
#define S2_BH 34816
#define S2_BL 43520
#define SMEM_WORDS 52224      // 208896 bytes

// ---------------- kernel 1: zero scratch ----------------
__global__ void zero_kernel(int N) {
    size_t total4 = (size_t)N * (FD / 4);
    float4 z = make_float4(0.f, 0.f, 0.f, 0.f);
    float4* s4 = (float4*)g_sum;
    for (size_t i = (size_t)blockIdx.x * blockDim.x + threadIdx.x; i < total4;
         i += (size_t)gridDim.x * blockDim.x)
        s4[i] = z;
    for (int i = blockIdx.x * blockDim.x + threadIdx.x; i < N;
         i += gridDim.x * blockDim.x)
        g_cnt[i] = 0;
}

// ---------------- kernel 2: scatter mean via vector RED ----------------
__global__ void scatter_kernel(const float* __restrict__ efeats,
                               const int* __restrict__ v, int E) {
    int w = (blockIdx.x * blockDim.x + threadIdx.x) >> 5;
    int lane = threadIdx.x & 31;
    if (w >= E) return;
    int dst = __ldg(&v[w]);
    float4 val = __ldg(((const float4*)(efeats + (size_t)w * FD)) + lane);
    float* s = g_sum + (size_t)dst * FD + lane * 4;
    asm volatile("red.global.add.v4.f32 [%0], {%1, %2, %3, %4};"
                 :: "l"(s), "f"(val.x), "f"(val.y), "f"(val.z), "f"(val.w)
                 : "memory");
    if (lane == 0) atomicAdd(&g_cnt[dst], 1);
}

// ---------------- kernel 3b: pack Wcat = [W_u ; W_v] ----------------
__global__ void wpack_kernel(const float* __restrict__ W_edge_w) {
    int t = blockIdx.x * blockDim.x + threadIdx.x;
    if (t >= 512 * 32) return;
    int n = t >> 5;
    int kq = t & 31;
    const float* src = (n < 256) ? (W_edge_w + (size_t)n * 256 + kq * 4)
                                 : (W_edge_w + (size_t)(n - 256) * 256 + 128 + kq * 4);
    ((float4*)g_Wcat)[t] = *(const float4*)src;
}

// ---------------- fused tf32x3 mma.sync GEMM -------------------------------
// stage A: h = relu([nfeats|mean] @ Wa^T + b)   (128 rows/CTA, N=128, K=256)
// stage B: P = h @ Wcat^T                       (N=512 as 4 quarters, K=128)
__global__ __launch_bounds__(256, 1) void gemm_tc_kernel(
    const float* __restrict__ nfeats,  // [M][128]
    const float* __restrict__ Wa,      // [128][256]
    const float* __restrict__ Wab,     // [128]
    float* __restrict__ h_out,         // [M][128]
    int M)
{
    extern __shared__ float sm[];
    const int tid = threadIdx.x;
    const int lane = tid & 31, wid = tid >> 5;
    const int warp_m = wid >> 2;          // 0..1 -> m offset 64*warp_m
    const int warp_n = wid & 3;           // 0..3 -> n offset 32*warp_n
    const int lq = lane >> 2, lr = lane & 3;
    const int bm = blockIdx.x * 128;

    float acc[4][4][4];                   // [mt][nt][c0..c3]
#pragma unroll
    for (int a = 0; a < 4; a++)
#pragma unroll
        for (int b = 0; b < 4; b++)
#pragma unroll
            for (int c = 0; c < 4; c++) acc[a][b][c] = 0.f;

    // one k8 mma step: A rows from Ah/Al, B rows from Bh/Bl (both [k][x], stride 136)
    auto mma_step = [&](const float* Ah, const float* Al,
                        const float* Bh, const float* Bl, int kk) {
        uint32_t ah[4][4], al[4][4], bh[4][2], bl[4][2];
        const int r0 = (kk + lr) * SMS;
        const int r4 = r0 + 4 * SMS;
#pragma unroll
        for (int mt = 0; mt < 4; mt++) {
            int m0 = warp_m * 64 + mt * 16 + lq;
            ah[mt][0] = __float_as_uint(Ah[r0 + m0]);
            ah[mt][1] = __float_as_uint(Ah[r0 + m0 + 8]);
            ah[mt][2] = __float_as_uint(Ah[r4 + m0]);
            ah[mt][3] = __float_as_uint(Ah[r4 + m0 + 8]);
            al[mt][0] = __float_as_uint(Al[r0 + m0]);
            al[mt][1] = __float_as_uint(Al[r0 + m0 + 8]);
            al[mt][2] = __float_as_uint(Al[r4 + m0]);
            al[mt][3] = __float_as_uint(Al[r4 + m0 + 8]);
        }
#pragma unroll
        for (int nt = 0; nt < 4; nt++) {
            int n0 = warp_n * 32 + nt * 8 + lq;
            bh[nt][0] = __float_as_uint(Bh[r0 + n0]);
            bh[nt][1] = __float_as_uint(Bh[r4 + n0]);
            bl[nt][0] = __float_as_uint(Bl[r0 + n0]);
            bl[nt][1] = __float_as_uint(Bl[r4 + n0]);
        }
#pragma unroll
        for (int mt = 0; mt < 4; mt++)
#pragma unroll
            for (int nt = 0; nt < 4; nt++) {
                mma_m16n8k8(acc[mt][nt], ah[mt], bh[nt]);
                mma_m16n8k8(acc[mt][nt], ah[mt], bl[nt]);
                mma_m16n8k8(acc[mt][nt], al[mt], bh[nt]);
            }
    };

    // ================= stage A: 4 K-chunks of 64 =================
#pragma unroll 1
    for (int c = 0; c < 4; c++) {
        if (c) __syncthreads();           // prior chunk's mma reads done
        const int kbase = c * 64;
        // cooperative load + tf32-split. Slot: row = s&127 (lane-consecutive ->
        // conflict-free STS), c4 = s>>7 (k float4 index).
#pragma unroll
        for (int i = 0; i < 8; i++) {
            int s = tid + i * 256;
            int row = s & 127;
            int c4 = s >> 7;
            int kg = kbase + c4 * 4;
            float4 av = make_float4(0.f, 0.f, 0.f, 0.f);
            int gm = bm + row;
            if (gm < M) {
                if (kbase < 128) {
                    av = *(const float4*)(nfeats + (size_t)gm * 128 + kg);
                } else {
                    av = *(const float4*)(g_sum + (size_t)gm * 128 + (kg - 128));
                    float inv = 1.0f / fmaxf((float)__ldg(&g_cnt[gm]), 1.0f);
                    av.x *= inv; av.y *= inv; av.z *= inv; av.w *= inv;
                }
            }
            float4 bv = *(const float4*)(Wa + (size_t)row * 256 + kg);
            float aa[4] = {av.x, av.y, av.z, av.w};
            float bb[4] = {bv.x, bv.y, bv.z, bv.w};
#pragma unroll
            for (int j = 0; j < 4; j++) {
                int kr = c4 * 4 + j;
                uint32_t h_, l_;
                split_tf32(aa[j], h_, l_);
                sm[S1_AH + kr * SMS + row] = __uint_as_float(h_);
                sm[S1_AL + kr * SMS + row] = __uint_as_float(l_);
                split_tf32(bb[j], h_, l_);
                sm[S1_BH + kr * SMS + row] = __uint_as_float(h_);
                sm[S1_BL + kr * SMS + row] = __uint_as_float(l_);
            }
        }
        __syncthreads();
#pragma unroll
        for (int k8 = 0; k8 < 8; k8++)
            mma_step(sm + S1_AH, sm + S1_AL, sm + S1_BH, sm + S1_BL, k8 * 8);
    }
    __syncthreads();   // all stage-A mma reads done before h_s overwrite

    // ============ stage A epilogue: bias+relu, STG h, split h into smem ======
#pragma unroll
    for (int mt = 0; mt < 4; mt++) {
#pragma unroll
        for (int nt = 0; nt < 4; nt++) {
            int m = warp_m * 64 + mt * 16 + lq;
            int col = warp_n * 32 + nt * 8 + lr * 2;
            float b0 = __ldg(&Wab[col]);
            float b1 = __ldg(&Wab[col + 1]);
            float v00 = fmaxf(acc[mt][nt][0] + b0, 0.f);
            float v01 = fmaxf(acc[mt][nt][1] + b1, 0.f);
            float v10 = fmaxf(acc[mt][nt][2] + b0, 0.f);
            float v11 = fmaxf(acc[mt][nt][3] + b1, 0.f);
            int gm0 = bm + m, gm1 = bm + m + 8;
            if (gm0 < M)
                __stcs((float2*)(h_out + (size_t)gm0 * HD + col), make_float2(v00, v01));
            if (gm1 < M)
                __stcs((float2*)(h_out + (size_t)gm1 * HD + col), make_float2(v10, v11));
            uint32_t h_, l_;
            split_tf32(v00, h_, l_);
            sm[HS_H + col * SMS + m] = __uint_as_float(h_);
            sm[HS_L + col * SMS + m] = __uint_as_float(l_);
            split_tf32(v01, h_, l_);
            sm[HS_H + (col + 1) * SMS + m] = __uint_as_float(h_);
            sm[HS_L + (col + 1) * SMS + m] = __uint_as_float(l_);
            split_tf32(v10, h_, l_);
            sm[HS_H + col * SMS + m + 8] = __uint_as_float(h_);
            sm[HS_L + col * SMS + m + 8] = __uint_as_float(l_);
            split_tf32(v11, h_, l_);
            sm[HS_H + (col + 1) * SMS + m + 8] = __uint_as_float(h_);
            sm[HS_L + (col + 1) * SMS + m + 8] = __uint_as_float(l_);
        }
    }
    __syncthreads();   // h_s visible to all warps

    // ================= stage B: 4 quarters x 2 K-chunks of 64 ================
#pragma unroll 1
    for (int q = 0; q < 4; q++) {
#pragma unroll
        for (int a = 0; a < 4; a++)
#pragma unroll
            for (int b = 0; b < 4; b++)
#pragma unroll
                for (int c = 0; c < 4; c++) acc[a][b][c] = 0.f;

#pragma unroll 1
        for (int c = 0; c < 2; c++) {
            __syncthreads();   // prior chunk's Bs2 readers done
#pragma unroll
            for (int i = 0; i < 8; i++) {
                int s = tid + i * 256;
                int row = s & 127;         // n within quarter
                int c4 = s >> 7;
                int kg = c * 64 + c4 * 4;
                float4 bv = *(const float4*)(g_Wcat +
                              (size_t)(q * 128 + row) * 128 + kg);
                float bb[4] = {bv.x, bv.y, bv.z, bv.w};
#pragma unroll
                for (int j = 0; j < 4; j++) {
                    int kr = c4 * 4 + j;
                    uint32_t h_, l_;
                    split_tf32(bb[j], h_, l_);
                    sm[S2_BH + kr * SMS + row] = __uint_as_float(h_);
                    sm[S2_BL + kr * SMS + row] = __uint_as_float(l_);
                }
            }
            __syncthreads();
#pragma unroll
            for (int k8 = 0; k8 < 8; k8++)
                mma_step(sm + HS_H + c * 64 * SMS, sm + HS_L + c * 64 * SMS,
                         sm + S2_BH, sm + S2_BL, k8 * 8);
        }

        // epilogue: write quarter q of P
#pragma unroll
        for (int mt = 0; mt < 4; mt++) {
#pragma unroll
            for (int nt = 0; nt < 4; nt++) {
                int m = warp_m * 64 + mt * 16 + lq;
                int col = q * 128 + warp_n * 32 + nt * 8 + lr * 2;
                int gm0 = bm + m, gm1 = bm + m + 8;
                if (gm0 < M)
                    *(float2*)(g_P + (size_t)gm0 * 512 + col) =
                        make_float2(acc[mt][nt][0], acc[mt][nt][1]);
                if (gm1 < M)
                    *(float2*)(g_P + (size_t)gm1 * 512 + col) =
                        make_float2(acc[mt][nt][2], acc[mt][nt][3]);
            }
        }
    }
}

// ---------------- edge output = P_u[u] + P_v[v] + b ----------------
__global__ void edge_kernel(const int* __restrict__ u,
                            const int* __restrict__ v,
                            const float* __restrict__ W_edge_b,
                            float* __restrict__ out, int E) {
    int w = (blockIdx.x * blockDim.x + threadIdx.x) >> 5;
    int lane = threadIdx.x & 31;
    if (w >= E) return;
    int uu = __ldg(&u[w]);
    int vv = __ldg(&v[w]);
    const float4* pu = (const float4*)(g_P + (size_t)uu * 512);
    const float4* pv = (const float4*)(g_P + (size_t)vv * 512 + 256);
    const float4* b4 = (const float4*)W_edge_b;
    float4* o4 = (float4*)(out + (size_t)w * OD);
#pragma unroll
    for (int i = 0; i < 2; i++) {
        int idx = lane + i * 32;
        float4 a = pu[idx];
        float4 c = pv[idx];
        float4 bb = __ldg(&b4[idx]);
        float4 r = make_float4(a.x + c.x + bb.x, a.y + c.y + bb.y,
                               a.z + c.z + bb.z, a.w + c.w + bb.w);
        __stcs(&o4[idx], r);
    }
}

// ---------------- launcher ----------------
extern "C" void kernel_launch(void* const* d_in, const int* in_sizes, int n_in,
                              void* d_out, int out_size) {
    const float* nfeats    = (const float*)d_in[0];
    const float* efeats    = (const float*)d_in[1];
    const int*   u         = (const int*)d_in[2];
    const int*   v         = (const int*)d_in[3];
    const float* W_apply_w = (const float*)d_in[4];
    const float* W_apply_b = (const float*)d_in[5];
    const float* W_edge_w  = (const float*)d_in[6];
    const float* W_edge_b  = (const float*)d_in[7];
    (void)n_in; (void)out_size;

    const int N = in_sizes[0] / FD;   // 50000
    const int E = in_sizes[2];        // 800000

    float* h_out    = (float*)d_out;
    float* edge_out = (float*)d_out + (size_t)N * HD;

    zero_kernel<<<512, 512>>>(N);

    {
        int blocks = (E + 7) / 8;
        scatter_kernel<<<blocks, 256>>>(efeats, v, E);
    }

    wpack_kernel<<<(512 * 32 + 255) / 256, 256>>>(W_edge_w);

    {
        const int smem_bytes = SMEM_WORDS * (int)sizeof(float);  // 208896
        cudaFuncSetAttribute(gemm_tc_kernel,
                             cudaFuncAttributeMaxDynamicSharedMemorySize, smem_bytes);
        int grid = (N + 127) / 128;
        gemm_tc_kernel<<<grid, 256, smem_bytes>>>(nfeats, W_apply_w, W_apply_b,
                                                  h_out, N);
    }

    {
        int blocks = (E + 7) / 8;
        edge_kernel<<<blocks, 256>>>(u, v, W_edge_b, edge_out, E);
    }
}

// round 16
// speedup vs baseline: 1.0951x; 1.0951x over previous
#include <cuda_runtime.h>
#include <cuda_bf16.h>
#include <cstdint>

#define MAXN 50000
#define MAXE 800000
#define FD   128
#define HD   128
#define OD   256

// ---------------- device scratch ----------------
__device__ float g_sum[(size_t)MAXN * FD];
__device__ int   g_cnt[MAXN];
__device__ float g_P[(size_t)MAXN * 512];
__device__ float g_Wcat[512 * 128];

// ---------------- tf32 helpers (baseline PTX, compute_103-safe) -----------
__device__ __forceinline__ void split_tf32(float x, uint32_t& hi, uint32_t& lo) {
    asm("cvt.rna.tf32.f32 %0, %1;" : "=r"(hi) : "f"(x));
    float r = x - __uint_as_float(hi);
    asm("cvt.rna.tf32.f32 %0, %1;" : "=r"(lo) : "f"(r));
}
__device__ __forceinline__ void split4(float4 v, uint4& h4, uint4& l4) {
    split_tf32(v.x, h4.x, l4.x); split_tf32(v.y, h4.y, l4.y);
    split_tf32(v.z, h4.z, l4.z); split_tf32(v.w, h4.w, l4.w);
}
__device__ __forceinline__ void mma_m16n8k8(float* c, const uint32_t* a,
                                            const uint32_t* b) {
    asm volatile(
        "mma.sync.aligned.m16n8k8.row.col.f32.tf32.tf32.f32 "
        "{%0,%1,%2,%3}, {%4,%5,%6,%7}, {%8,%9}, {%0,%1,%2,%3};"
        : "+f"(c[0]), "+f"(c[1]), "+f"(c[2]), "+f"(c[3])
        : "r"(a[0]), "r"(a[1]), "r"(a[2]), "r"(a[3]), "r"(b[0]), "r"(b[1]));
}

// ---------------- smem layout (float words) -------------------------------
// stage-A tiles: [128 rows][32 k] stride 36 (banks 4*lq+lr distinct)
#define SA_AH 0
#define SA_AL 4608
#define SA_BH 9216
#define SA_BL 13824
// stage-B B tiles alias stage-A region (stage A fully drained first)
#define SB_BH 0
#define SB_BL 4608
// h tiles: [128 m][128 k] stride 132
#define H_H   18432
#define H_L   35328
#define SMEM_WORDS 52224      // 208896 bytes

// ---------------- kernel 1: zero scratch ----------------
__global__ void zero_kernel(int N) {
    size_t total4 = (size_t)N * (FD / 4);
    float4 z = make_float4(0.f, 0.f, 0.f, 0.f);
    float4* s4 = (float4*)g_sum;
    for (size_t i = (size_t)blockIdx.x * blockDim.x + threadIdx.x; i < total4;
         i += (size_t)gridDim.x * blockDim.x)
        s4[i] = z;
    for (int i = blockIdx.x * blockDim.x + threadIdx.x; i < N;
         i += gridDim.x * blockDim.x)
        g_cnt[i] = 0;
}

// ---------------- kernel 2: scatter mean via vector RED ----------------
__global__ void scatter_kernel(const float* __restrict__ efeats,
                               const int* __restrict__ v, int E) {
    int w = (blockIdx.x * blockDim.x + threadIdx.x) >> 5;
    int lane = threadIdx.x & 31;
    if (w >= E) return;
    int dst = __ldg(&v[w]);
    float4 val = __ldg(((const float4*)(efeats + (size_t)w * FD)) + lane);
    float* s = g_sum + (size_t)dst * FD + lane * 4;
    asm volatile("red.global.add.v4.f32 [%0], {%1, %2, %3, %4};"
                 :: "l"(s), "f"(val.x), "f"(val.y), "f"(val.z), "f"(val.w)
                 : "memory");
    if (lane == 0) atomicAdd(&g_cnt[dst], 1);
}

// ---------------- kernel 3b: pack Wcat = [W_u ; W_v] ----------------
__global__ void wpack_kernel(const float* __restrict__ W_edge_w) {
    int t = blockIdx.x * blockDim.x + threadIdx.x;
    if (t >= 512 * 32) return;
    int n = t >> 5;
    int kq = t & 31;
    const float* src = (n < 256) ? (W_edge_w + (size_t)n * 256 + kq * 4)
                                 : (W_edge_w + (size_t)(n - 256) * 256 + 128 + kq * 4);
    ((float4*)g_Wcat)[t] = *(const float4*)src;
}

// ---------------- fused tf32x3 mma.sync GEMM, pipelined --------------------
// stage A: h = relu([nfeats|mean] @ Wa^T + b)   (128 rows/CTA, N=128, K=256)
// stage B: P = h @ Wcat^T                       (N=512 as 4 quarters, K=128)
// 512 threads, 16 warps in 4m x 4n grid, 32x32 warp tile.
__global__ __launch_bounds__(512, 1) void gemm_tc_kernel(
    const float* __restrict__ nfeats,  // [M][128]
    const float* __restrict__ Wa,      // [128][256]
    const float* __restrict__ Wab,     // [128]
    float* __restrict__ h_out,         // [M][128]
    int M)
{
    extern __shared__ float sm[];
    const int tid = threadIdx.x;
    const int lane = tid & 31, wid = tid >> 5;
    const int warp_m = wid & 3;          // m offset 32*warp_m
    const int warp_n = wid >> 2;         // n offset 32*warp_n
    const int lq = lane >> 2, lr = lane & 3;
    const int bm = blockIdx.x * 128;

    // loader slots: 1024 float4 per tile, 2 per thread
    const int row0 = tid >> 3,            c40 = tid & 7;
    const int row1 = (tid + 512) >> 3,    c41 = (tid + 512) & 7;

    float acc[2][4][4];
#pragma unroll
    for (int a = 0; a < 2; a++)
#pragma unroll
        for (int b = 0; b < 4; b++)
#pragma unroll
            for (int c = 0; c < 4; c++) acc[a][b][c] = 0.f;

    float4 stA[2], stB[2];

    // ---- staging loads ----
    auto ldgA = [&](int cki) {          // virtual cat A tile, chunk cki (k=32)
#pragma unroll
        for (int i = 0; i < 2; i++) {
            int row = i ? row1 : row0;
            int c4  = i ? c41  : c40;
            int kg = cki * 32 + c4 * 4;
            int gm = bm + row;
            float4 v = make_float4(0.f, 0.f, 0.f, 0.f);
            if (gm < M) {
                if (cki < 4) {
                    v = *(const float4*)(nfeats + (size_t)gm * 128 + kg);
                } else {
                    v = *(const float4*)(g_sum + (size_t)gm * 128 + (kg - 128));
                    float inv = 1.0f / fmaxf((float)__ldg(&g_cnt[gm]), 1.0f);
                    v.x *= inv; v.y *= inv; v.z *= inv; v.w *= inv;
                }
            }
            stA[i] = v;
        }
    };
    auto ldgB1 = [&](int cki) {         // Wa B tile
#pragma unroll
        for (int i = 0; i < 2; i++) {
            int row = i ? row1 : row0;
            int c4  = i ? c41  : c40;
            stB[i] = *(const float4*)(Wa + (size_t)row * 256 + cki * 32 + c4 * 4);
        }
    };
    auto ldgB2 = [&](int q, int cc) {   // Wcat quarter-q B tile
#pragma unroll
        for (int i = 0; i < 2; i++) {
            int row = i ? row1 : row0;
            int c4  = i ? c41  : c40;
            stB[i] = *(const float4*)(g_Wcat +
                       (size_t)(q * 128 + row) * 128 + cc * 32 + c4 * 4);
        }
    };
    auto stsA = [&]() {
#pragma unroll
        for (int i = 0; i < 2; i++) {
            int row = i ? row1 : row0;
            int c4  = i ? c41  : c40;
            uint4 h4, l4; split4(stA[i], h4, l4);
            int off = row * 36 + c4 * 4;
            *(uint4*)&sm[SA_AH + off] = h4;
            *(uint4*)&sm[SA_AL + off] = l4;
        }
    };
    auto stsB = [&](int base_h, int base_l) {
#pragma unroll
        for (int i = 0; i < 2; i++) {
            int row = i ? row1 : row0;
            int c4  = i ? c41  : c40;
            uint4 h4, l4; split4(stB[i], h4, l4);
            int off = row * 36 + c4 * 4;
            *(uint4*)&sm[base_h + off] = h4;
            *(uint4*)&sm[base_l + off] = l4;
        }
    };

    // ---- one k8 mma step ----
    auto mma_step = [&](const float* Ah, const float* Al, int aS,
                        const float* Bh, const float* Bl, int bS,
                        int ka, int kb) {
        uint32_t ah[2][4], al[2][4], bh[4][2], bl[4][2];
#pragma unroll
        for (int mt = 0; mt < 2; mt++) {
            int m0 = warp_m * 32 + mt * 16 + lq;
            ah[mt][0] = __float_as_uint(Ah[m0 * aS + ka + lr]);
            ah[mt][1] = __float_as_uint(Ah[(m0 + 8) * aS + ka + lr]);
            ah[mt][2] = __float_as_uint(Ah[m0 * aS + ka + lr + 4]);
            ah[mt][3] = __float_as_uint(Ah[(m0 + 8) * aS + ka + lr + 4]);
            al[mt][0] = __float_as_uint(Al[m0 * aS + ka + lr]);
            al[mt][1] = __float_as_uint(Al[(m0 + 8) * aS + ka + lr]);
            al[mt][2] = __float_as_uint(Al[m0 * aS + ka + lr + 4]);
            al[mt][3] = __float_as_uint(Al[(m0 + 8) * aS + ka + lr + 4]);
        }
#pragma unroll
        for (int nt = 0; nt < 4; nt++) {
            int n0 = warp_n * 32 + nt * 8 + lq;
            bh[nt][0] = __float_as_uint(Bh[n0 * bS + kb + lr]);
            bh[nt][1] = __float_as_uint(Bh[n0 * bS + kb + lr + 4]);
            bl[nt][0] = __float_as_uint(Bl[n0 * bS + kb + lr]);
            bl[nt][1] = __float_as_uint(Bl[n0 * bS + kb + lr + 4]);
        }
#pragma unroll
        for (int mt = 0; mt < 2; mt++)
#pragma unroll
            for (int nt = 0; nt < 4; nt++) {
                mma_m16n8k8(acc[mt][nt], ah[mt], bh[nt]);
                mma_m16n8k8(acc[mt][nt], ah[mt], bl[nt]);
                mma_m16n8k8(acc[mt][nt], al[mt], bh[nt]);
            }
    };

    // ================= stage A: 8 chunks of k=32, reg-staged pipeline =======
    ldgA(0); ldgB1(0);
#pragma unroll 1
    for (int c = 0; c < 8; c++) {
        if (c) __syncthreads();          // prior chunk's mma reads done
        stsA();
        stsB(SA_BH, SA_BL);
        __syncthreads();
        if (c < 7) { ldgA(c + 1); ldgB1(c + 1); }   // LDG overlaps mma
#pragma unroll
        for (int k8 = 0; k8 < 4; k8++)
            mma_step(sm + SA_AH, sm + SA_AL, 36,
                     sm + SA_BH, sm + SA_BL, 36, k8 * 8, k8 * 8);
    }

    // prefetch stage-B chunk 0 while doing the epilogue
    ldgB2(0, 0);

    // ===== stage A epilogue: bias+relu, STG h, split h into smem [m][k] =====
#pragma unroll
    for (int mt = 0; mt < 2; mt++) {
#pragma unroll
        for (int nt = 0; nt < 4; nt++) {
            int m = warp_m * 32 + mt * 16 + lq;
            int col = warp_n * 32 + nt * 8 + lr * 2;
            float b0 = __ldg(&Wab[col]);
            float b1 = __ldg(&Wab[col + 1]);
            float v00 = fmaxf(acc[mt][nt][0] + b0, 0.f);
            float v01 = fmaxf(acc[mt][nt][1] + b1, 0.f);
            float v10 = fmaxf(acc[mt][nt][2] + b0, 0.f);
            float v11 = fmaxf(acc[mt][nt][3] + b1, 0.f);
            int gm0 = bm + m, gm1 = bm + m + 8;
            if (gm0 < M)
                __stcs((float2*)(h_out + (size_t)gm0 * HD + col), make_float2(v00, v01));
            if (gm1 < M)
                __stcs((float2*)(h_out + (size_t)gm1 * HD + col), make_float2(v10, v11));
            uint32_t h0, l0, h1, l1;
            split_tf32(v00, h0, l0); split_tf32(v01, h1, l1);
            *(float2*)&sm[H_H + m * 132 + col] =
                make_float2(__uint_as_float(h0), __uint_as_float(h1));
            *(float2*)&sm[H_L + m * 132 + col] =
                make_float2(__uint_as_float(l0), __uint_as_float(l1));
            split_tf32(v10, h0, l0); split_tf32(v11, h1, l1);
            *(float2*)&sm[H_H + (m + 8) * 132 + col] =
                make_float2(__uint_as_float(h0), __uint_as_float(h1));
            *(float2*)&sm[H_L + (m + 8) * 132 + col] =
                make_float2(__uint_as_float(l0), __uint_as_float(l1));
        }
    }
    __syncthreads();   // stage-A mma + h_s writes complete; SA region now free

    // ================= stage B: 4 quarters x 4 chunks of k=32 ===============
#pragma unroll 1
    for (int it = 0; it < 16; it++) {
        int q = it >> 2, cc = it & 3;
        if ((it & 3) == 0) {
#pragma unroll
            for (int a = 0; a < 2; a++)
#pragma unroll
                for (int b = 0; b < 4; b++)
#pragma unroll
                    for (int c = 0; c < 4; c++) acc[a][b][c] = 0.f;
        }
        if (it) __syncthreads();
        stsB(SB_BH, SB_BL);
        __syncthreads();
        if (it < 15) ldgB2((it + 1) >> 2, (it + 1) & 3);
#pragma unroll
        for (int k8 = 0; k8 < 4; k8++)
            mma_step(sm + H_H, sm + H_L, 132,
                     sm + SB_BH, sm + SB_BL, 36, cc * 32 + k8 * 8, k8 * 8);
        if (cc == 3) {
            // write quarter q of P
#pragma unroll
            for (int mt = 0; mt < 2; mt++) {
#pragma unroll
                for (int nt = 0; nt < 4; nt++) {
                    int m = warp_m * 32 + mt * 16 + lq;
                    int col = q * 128 + warp_n * 32 + nt * 8 + lr * 2;
                    int gm0 = bm + m, gm1 = bm + m + 8;
                    if (gm0 < M)
                        *(float2*)(g_P + (size_t)gm0 * 512 + col) =
                            make_float2(acc[mt][nt][0], acc[mt][nt][1]);
                    if (gm1 < M)
                        *(float2*)(g_P + (size_t)gm1 * 512 + col) =
                            make_float2(acc[mt][nt][2], acc[mt][nt][3]);
                }
            }
        }
    }
}

// ---------------- edge output = P_u[u] + P_v[v] + b ----------------
__global__ void edge_kernel(const int* __restrict__ u,
                            const int* __restrict__ v,
                            const float* __restrict__ W_edge_b,
                            float* __restrict__ out, int E) {
    int w = (blockIdx.x * blockDim.x + threadIdx.x) >> 5;
    int lane = threadIdx.x & 31;
    if (w >= E) return;
    int uu = __ldg(&u[w]);
    int vv = __ldg(&v[w]);
    const float4* pu = (const float4*)(g_P + (size_t)uu * 512);
    const float4* pv = (const float4*)(g_P + (size_t)vv * 512 + 256);
    const float4* b4 = (const float4*)W_edge_b;
    float4* o4 = (float4*)(out + (size_t)w * OD);
#pragma unroll
    for (int i = 0; i < 2; i++) {
        int idx = lane + i * 32;
        float4 a = pu[idx];
        float4 c = pv[idx];
        float4 bb = __ldg(&b4[idx]);
        float4 r = make_float4(a.x + c.x + bb.x, a.y + c.y + bb.y,
                               a.z + c.z + bb.z, a.w + c.w + bb.w);
        __stcs(&o4[idx], r);
    }
}

// ---------------- launcher ----------------
extern "C" void kernel_launch(void* const* d_in, const int* in_sizes, int n_in,
                              void* d_out, int out_size) {
    const float* nfeats    = (const float*)d_in[0];
    const float* efeats    = (const float*)d_in[1];
    const int*   u         = (const int*)d_in[2];
    const int*   v         = (const int*)d_in[3];
    const float* W_apply_w = (const float*)d_in[4];
    const float* W_apply_b = (const float*)d_in[5];
    const float* W_edge_w  = (const float*)d_in[6];
    const float* W_edge_b  = (const float*)d_in[7];
    (void)n_in; (void)out_size;

    const int N = in_sizes[0] / FD;   // 50000
    const int E = in_sizes[2];        // 800000

    float* h_out    = (float*)d_out;
    float* edge_out = (float*)d_out + (size_t)N * HD;

    zero_kernel<<<512, 512>>>(N);

    {
        int blocks = (E + 7) / 8;
        scatter_kernel<<<blocks, 256>>>(efeats, v, E);
    }

    wpack_kernel<<<(512 * 32 + 255) / 256, 256>>>(W_edge_w);

    {
        const int smem_bytes = SMEM_WORDS * (int)sizeof(float);  // 208896
        cudaFuncSetAttribute(gemm_tc_kernel,
                             cudaFuncAttributeMaxDynamicSharedMemorySize, smem_bytes);
        int grid = (N + 127) / 128;
        gemm_tc_kernel<<<grid, 512, smem_bytes>>>(nfeats, W_apply_w, W_apply_b,
                                                  h_out, N);
    }

    {
        int blocks = (E + 7) / 8;
        edge_kernel<<<blocks, 256>>>(u, v, W_edge_b, edge_out, E);
    }
}

// round 17
// speedup vs baseline: 1.2497x; 1.1412x over previous
#include <cuda_runtime.h>
#include <cuda_bf16.h>
#include <cstdint>

#define MAXN 50000
#define MAXE 800000
#define FD   128
#define HD   128
#define OD   256

// ---------------- device scratch ----------------
__device__ float g_sum[(size_t)MAXN * FD];
__device__ int   g_cnt[MAXN];
__device__ float g_P[(size_t)MAXN * 512];
__device__ float g_Wcat[512 * 128];

// ---------------- bf16 split helpers (baseline PTX) ----------------
__device__ __forceinline__ uint32_t bf16_bits(float x) {
    __nv_bfloat16 b = __float2bfloat16_rn(x);
    return (uint32_t)*(uint16_t*)&b;
}
__device__ __forceinline__ void split_bf(float x, uint32_t& hb, uint32_t& lb) {
    hb = bf16_bits(x);
    float hf = __uint_as_float(hb << 16);   // exact bf16 -> f32
    lb = bf16_bits(x - hf);
}
// float4 (4 consecutive k) -> 2 packed hi words + 2 packed lo words
__device__ __forceinline__ void split_f4(float4 v, uint2& hw, uint2& lw) {
    uint32_t h0, l0, h1, l1, h2, l2, h3, l3;
    split_bf(v.x, h0, l0); split_bf(v.y, h1, l1);
    split_bf(v.z, h2, l2); split_bf(v.w, h3, l3);
    hw.x = h0 | (h1 << 16); hw.y = h2 | (h3 << 16);
    lw.x = l0 | (l1 << 16); lw.y = l2 | (l3 << 16);
}
__device__ __forceinline__ void mma_bf16(float* c, const uint32_t* a,
                                         const uint32_t* b) {
    asm volatile(
        "mma.sync.aligned.m16n8k16.row.col.f32.bf16.bf16.f32 "
        "{%0,%1,%2,%3}, {%4,%5,%6,%7}, {%8,%9}, {%0,%1,%2,%3};"
        : "+f"(c[0]), "+f"(c[1]), "+f"(c[2]), "+f"(c[3])
        : "r"(a[0]), "r"(a[1]), "r"(a[2]), "r"(a[3]), "r"(b[0]), "r"(b[1]));
}

// ---------------- smem layout (32-bit words) ------------------------------
// stage-A tiles: [128 rows][16 kpair words]+4 pad -> stride 20 (conflict-free)
#define SA_BUF 10240     // AH | AL | BH | BL, 2560 words each; 2 buffers
#define H_H    20480     // h tiles [128 m][64 kpair]+4 pad -> stride 68
#define H_L    29184
#define SB_BUF 9216      // stage-B B tiles [128 n][32 kpair]+4 pad -> stride 36
#define SMEM_WORDS 37888 // 151552 bytes

// ---------------- kernel 1: zero scratch ----------------
__global__ void zero_kernel(int N) {
    size_t total4 = (size_t)N * (FD / 4);
    float4 z = make_float4(0.f, 0.f, 0.f, 0.f);
    float4* s4 = (float4*)g_sum;
    for (size_t i = (size_t)blockIdx.x * blockDim.x + threadIdx.x; i < total4;
         i += (size_t)gridDim.x * blockDim.x)
        s4[i] = z;
    for (int i = blockIdx.x * blockDim.x + threadIdx.x; i < N;
         i += gridDim.x * blockDim.x)
        g_cnt[i] = 0;
}

// ---------------- kernel 2: scatter mean via vector RED ----------------
__global__ void scatter_kernel(const float* __restrict__ efeats,
                               const int* __restrict__ v, int E) {
    int w = (blockIdx.x * blockDim.x + threadIdx.x) >> 5;
    int lane = threadIdx.x & 31;
    if (w >= E) return;
    int dst = __ldg(&v[w]);
    float4 val = __ldg(((const float4*)(efeats + (size_t)w * FD)) + lane);
    float* s = g_sum + (size_t)dst * FD + lane * 4;
    asm volatile("red.global.add.v4.f32 [%0], {%1, %2, %3, %4};"
                 :: "l"(s), "f"(val.x), "f"(val.y), "f"(val.z), "f"(val.w)
                 : "memory");
    if (lane == 0) atomicAdd(&g_cnt[dst], 1);
}

// ---------------- kernel 3b: pack Wcat = [W_u ; W_v] ----------------
__global__ void wpack_kernel(const float* __restrict__ W_edge_w) {
    int t = blockIdx.x * blockDim.x + threadIdx.x;
    if (t >= 512 * 32) return;
    int n = t >> 5;
    int kq = t & 31;
    const float* src = (n < 256) ? (W_edge_w + (size_t)n * 256 + kq * 4)
                                 : (W_edge_w + (size_t)(n - 256) * 256 + 128 + kq * 4);
    ((float4*)g_Wcat)[t] = *(const float4*)src;
}

// ---------------- fused bf16x3 mma.sync GEMM, double-buffered --------------
// stage A: h = relu([nfeats|mean] @ Wa^T + b)   (128 rows/CTA, N=128, K=256)
// stage B: P = h @ Wcat^T                       (N=512 as 4 quarters, K=128)
// 512 threads, 16 warps in 4m x 4n grid, 32x32 warp tile, m16n8k16 bf16.
__global__ __launch_bounds__(512, 1) void gemm_tc_kernel(
    const float* __restrict__ nfeats,  // [M][128]
    const float* __restrict__ Wa,      // [128][256]
    const float* __restrict__ Wab,     // [128]
    float* __restrict__ h_out,         // [M][128]
    int M)
{
    extern __shared__ uint32_t smw[];
    const int tid = threadIdx.x;
    const int lane = tid & 31, wid = tid >> 5;
    const int warp_m = wid & 3;          // m offset 32*warp_m
    const int warp_n = wid >> 2;         // n offset 32*warp_n
    const int lq = lane >> 2, lr = lane & 3;
    const int bm = blockIdx.x * 128;

    // stage-A loader slots: 1024 float4 per tile, 2 per thread
    const int row0 = tid >> 3,         c40 = tid & 7;
    const int row1 = (tid + 512) >> 3, c41 = (tid + 512) & 7;

    float acc[2][4][4];
#pragma unroll
    for (int a = 0; a < 2; a++)
#pragma unroll
        for (int b = 0; b < 4; b++)
#pragma unroll
            for (int c = 0; c < 4; c++) acc[a][b][c] = 0.f;

    float4 stA[2], stB[2], stQ[4];

    auto ldgA1 = [&](int c) {            // A (virtual cat) + B (Wa), chunk k=32
#pragma unroll
        for (int i = 0; i < 2; i++) {
            int row = i ? row1 : row0;
            int c4  = i ? c41  : c40;
            int kg = c * 32 + c4 * 4;
            int gm = bm + row;
            float4 v = make_float4(0.f, 0.f, 0.f, 0.f);
            if (gm < M) {
                if (kg < 128) {
                    v = *(const float4*)(nfeats + (size_t)gm * 128 + kg);
                } else {
                    v = *(const float4*)(g_sum + (size_t)gm * 128 + kg - 128);
                    float inv = 1.0f / fmaxf((float)__ldg(&g_cnt[gm]), 1.0f);
                    v.x *= inv; v.y *= inv; v.z *= inv; v.w *= inv;
                }
            }
            stA[i] = v;
            stB[i] = *(const float4*)(Wa + (size_t)row * 256 + kg);
        }
    };
    auto stsA1 = [&](int buf) {
        uint32_t* base = smw + buf * SA_BUF;
#pragma unroll
        for (int i = 0; i < 2; i++) {
            int row = i ? row1 : row0;
            int c4  = i ? c41  : c40;
            int off = row * 20 + c4 * 2;
            uint2 hw, lw;
            split_f4(stA[i], hw, lw);
            *(uint2*)&base[off]        = hw;   // AH
            *(uint2*)&base[2560 + off] = lw;   // AL
            split_f4(stB[i], hw, lw);
            *(uint2*)&base[5120 + off] = hw;   // BH
            *(uint2*)&base[7680 + off] = lw;   // BL
        }
    };
    auto mmaA = [&](int buf, int step) { // one k16 step
        const uint32_t* AH = smw + buf * SA_BUF;
        const uint32_t* AL = AH + 2560;
        const uint32_t* BH = AH + 5120;
        const uint32_t* BL = AH + 7680;
        int kb = step * 8 + lr;
        uint32_t ah[2][4], al[2][4], bh[4][2], bl[4][2];
#pragma unroll
        for (int mt = 0; mt < 2; mt++) {
            int m0 = warp_m * 32 + mt * 16 + lq;
            ah[mt][0] = AH[m0 * 20 + kb];       ah[mt][1] = AH[(m0 + 8) * 20 + kb];
            ah[mt][2] = AH[m0 * 20 + kb + 4];   ah[mt][3] = AH[(m0 + 8) * 20 + kb + 4];
            al[mt][0] = AL[m0 * 20 + kb];       al[mt][1] = AL[(m0 + 8) * 20 + kb];
            al[mt][2] = AL[m0 * 20 + kb + 4];   al[mt][3] = AL[(m0 + 8) * 20 + kb + 4];
        }
#pragma unroll
        for (int nt = 0; nt < 4; nt++) {
            int n0 = warp_n * 32 + nt * 8 + lq;
            bh[nt][0] = BH[n0 * 20 + kb]; bh[nt][1] = BH[n0 * 20 + kb + 4];
            bl[nt][0] = BL[n0 * 20 + kb]; bl[nt][1] = BL[n0 * 20 + kb + 4];
        }
#pragma unroll
        for (int mt = 0; mt < 2; mt++)
#pragma unroll
            for (int nt = 0; nt < 4; nt++) {
                mma_bf16(acc[mt][nt], ah[mt], bh[nt]);
                mma_bf16(acc[mt][nt], ah[mt], bl[nt]);
                mma_bf16(acc[mt][nt], al[mt], bh[nt]);
            }
    };

    // ================= stage A: 8 chunks of k=32, double-buffered ===========
    ldgA1(0);
#pragma unroll 1
    for (int c = 0; c < 8; c++) {
        int buf = c & 1;
        stsA1(buf);
        __syncthreads();
        if (c < 7) ldgA1(c + 1);
        mmaA(buf, 0);
        mmaA(buf, 1);
    }

    // stage-B loader slots: 2048 float4 per chunk (k=64), 4 per thread
    auto ldgB2 = [&](int it) {
        int q = it >> 1, cc = it & 1;
#pragma unroll
        for (int i = 0; i < 4; i++) {
            int s = tid + i * 512;
            int row = s >> 4, c4 = s & 15;
            stQ[i] = *(const float4*)(g_Wcat + (size_t)(q * 128 + row) * 128 +
                                      cc * 64 + c4 * 4);
        }
    };
    ldgB2(0);   // prefetch while doing the epilogue

    // ===== stage A epilogue: bias+relu, STG h, pack h pairs into smem ======
#pragma unroll
    for (int mt = 0; mt < 2; mt++) {
#pragma unroll
        for (int nt = 0; nt < 4; nt++) {
            int m = warp_m * 32 + mt * 16 + lq;
            int col = warp_n * 32 + nt * 8 + lr * 2;
            float b0 = __ldg(&Wab[col]);
            float b1 = __ldg(&Wab[col + 1]);
            float v00 = fmaxf(acc[mt][nt][0] + b0, 0.f);
            float v01 = fmaxf(acc[mt][nt][1] + b1, 0.f);
            float v10 = fmaxf(acc[mt][nt][2] + b0, 0.f);
            float v11 = fmaxf(acc[mt][nt][3] + b1, 0.f);
            int gm0 = bm + m, gm1 = bm + m + 8;
            if (gm0 < M)
                __stcs((float2*)(h_out + (size_t)gm0 * HD + col), make_float2(v00, v01));
            if (gm1 < M)
                __stcs((float2*)(h_out + (size_t)gm1 * HD + col), make_float2(v10, v11));
            int widx = col >> 1;   // kpair index for stage B
            uint32_t h0, l0, h1, l1;
            split_bf(v00, h0, l0); split_bf(v01, h1, l1);
            smw[H_H + m * 68 + widx] = h0 | (h1 << 16);
            smw[H_L + m * 68 + widx] = l0 | (l1 << 16);
            split_bf(v10, h0, l0); split_bf(v11, h1, l1);
            smw[H_H + (m + 8) * 68 + widx] = h0 | (h1 << 16);
            smw[H_L + (m + 8) * 68 + widx] = l0 | (l1 << 16);
        }
    }
    __syncthreads();   // stage-A mma done (SA free), h tiles visible

    auto stsB2 = [&](int buf) {
        uint32_t* base = smw + buf * SB_BUF;
#pragma unroll
        for (int i = 0; i < 4; i++) {
            int s = tid + i * 512;
            int row = s >> 4, c4 = s & 15;
            int off = row * 36 + c4 * 2;
            uint2 hw, lw; split_f4(stQ[i], hw, lw);
            *(uint2*)&base[off]        = hw;   // BH
            *(uint2*)&base[4608 + off] = lw;   // BL
        }
    };
    auto mmaB = [&](int buf, int cc, int step) {
        const uint32_t* AH = smw + H_H;
        const uint32_t* AL = smw + H_L;
        const uint32_t* BH = smw + buf * SB_BUF;
        const uint32_t* BL = BH + 4608;
        int ka = cc * 32 + step * 8 + lr;
        int kb = step * 8 + lr;
        uint32_t ah[2][4], al[2][4], bh[4][2], bl[4][2];
#pragma unroll
        for (int mt = 0; mt < 2; mt++) {
            int m0 = warp_m * 32 + mt * 16 + lq;
            ah[mt][0] = AH[m0 * 68 + ka];       ah[mt][1] = AH[(m0 + 8) * 68 + ka];
            ah[mt][2] = AH[m0 * 68 + ka + 4];   ah[mt][3] = AH[(m0 + 8) * 68 + ka + 4];
            al[mt][0] = AL[m0 * 68 + ka];       al[mt][1] = AL[(m0 + 8) * 68 + ka];
            al[mt][2] = AL[m0 * 68 + ka + 4];   al[mt][3] = AL[(m0 + 8) * 68 + ka + 4];
        }
#pragma unroll
        for (int nt = 0; nt < 4; nt++) {
            int n0 = warp_n * 32 + nt * 8 + lq;
            bh[nt][0] = BH[n0 * 36 + kb]; bh[nt][1] = BH[n0 * 36 + kb + 4];
            bl[nt][0] = BL[n0 * 36 + kb]; bl[nt][1] = BL[n0 * 36 + kb + 4];
        }
#pragma unroll
        for (int mt = 0; mt < 2; mt++)
#pragma unroll
            for (int nt = 0; nt < 4; nt++) {
                mma_bf16(acc[mt][nt], ah[mt], bh[nt]);
                mma_bf16(acc[mt][nt], ah[mt], bl[nt]);
                mma_bf16(acc[mt][nt], al[mt], bh[nt]);
            }
    };

    // ============ stage B: 4 quarters x 2 chunks of k=64 ============
#pragma unroll 1
    for (int it = 0; it < 8; it++) {
        int q = it >> 1, cc = it & 1, buf = it & 1;
        if (cc == 0) {
#pragma unroll
            for (int a = 0; a < 2; a++)
#pragma unroll
                for (int b = 0; b < 4; b++)
#pragma unroll
                    for (int c = 0; c < 4; c++) acc[a][b][c] = 0.f;
        }
        stsB2(buf);
        __syncthreads();
        if (it < 7) ldgB2(it + 1);
#pragma unroll
        for (int s = 0; s < 4; s++) mmaB(buf, cc, s);
        if (cc == 1) {
#pragma unroll
            for (int mt = 0; mt < 2; mt++) {
#pragma unroll
                for (int nt = 0; nt < 4; nt++) {
                    int m = warp_m * 32 + mt * 16 + lq;
                    int col = q * 128 + warp_n * 32 + nt * 8 + lr * 2;
                    int gm0 = bm + m, gm1 = bm + m + 8;
                    if (gm0 < M)
                        *(float2*)(g_P + (size_t)gm0 * 512 + col) =
                            make_float2(acc[mt][nt][0], acc[mt][nt][1]);
                    if (gm1 < M)
                        *(float2*)(g_P + (size_t)gm1 * 512 + col) =
                            make_float2(acc[mt][nt][2], acc[mt][nt][3]);
                }
            }
        }
    }
}

// ---------------- edge output = P_u[u] + P_v[v] + b ----------------
__global__ void edge_kernel(const int* __restrict__ u,
                            const int* __restrict__ v,
                            const float* __restrict__ W_edge_b,
                            float* __restrict__ out, int E) {
    int w = (blockIdx.x * blockDim.x + threadIdx.x) >> 5;
    int lane = threadIdx.x & 31;
    if (w >= E) return;
    int uu = __ldg(&u[w]);
    int vv = __ldg(&v[w]);
    const float4* pu = (const float4*)(g_P + (size_t)uu * 512);
    const float4* pv = (const float4*)(g_P + (size_t)vv * 512 + 256);
    const float4* b4 = (const float4*)W_edge_b;
    float4* o4 = (float4*)(out + (size_t)w * OD);
#pragma unroll
    for (int i = 0; i < 2; i++) {
        int idx = lane + i * 32;
        float4 a = pu[idx];
        float4 c = pv[idx];
        float4 bb = __ldg(&b4[idx]);
        float4 r = make_float4(a.x + c.x + bb.x, a.y + c.y + bb.y,
                               a.z + c.z + bb.z, a.w + c.w + bb.w);
        __stcs(&o4[idx], r);
    }
}

// ---------------- launcher ----------------
extern "C" void kernel_launch(void* const* d_in, const int* in_sizes, int n_in,
                              void* d_out, int out_size) {
    const float* nfeats    = (const float*)d_in[0];
    const float* efeats    = (const float*)d_in[1];
    const int*   u         = (const int*)d_in[2];
    const int*   v         = (const int*)d_in[3];
    const float* W_apply_w = (const float*)d_in[4];
    const float* W_apply_b = (const float*)d_in[5];
    const float* W_edge_w  = (const float*)d_in[6];
    const float* W_edge_b  = (const float*)d_in[7];
    (void)n_in; (void)out_size;

    const int N = in_sizes[0] / FD;   // 50000
    const int E = in_sizes[2];        // 800000

    float* h_out    = (float*)d_out;
    float* edge_out = (float*)d_out + (size_t)N * HD;

    zero_kernel<<<512, 512>>>(N);

    {
        int blocks = (E + 7) / 8;
        scatter_kernel<<<blocks, 256>>>(efeats, v, E);
    }

    wpack_kernel<<<(512 * 32 + 255) / 256, 256>>>(W_edge_w);

    {
        const int smem_bytes = SMEM_WORDS * (int)sizeof(uint32_t);  // 151552
        cudaFuncSetAttribute(gemm_tc_kernel,
                             cudaFuncAttributeMaxDynamicSharedMemorySize, smem_bytes);
        int grid = (N + 127) / 128;
        gemm_tc_kernel<<<grid, 512, smem_bytes>>>(nfeats, W_apply_w, W_apply_b,
                                                  h_out, N);
    }

    {
        int blocks = (E + 7) / 8;
        edge_kernel<<<blocks, 256>>>(u, v, W_edge_b, edge_out, E);
    }
}